// round 13
// baseline (speedup 1.0000x reference)
#include <cuda_runtime.h>
#include <cuda_bf16.h>
#include <cstdint>

// ---------------------------------------------------------------------------
// DiffNet forward, batch-sparsified, ELL layout, FUSED spmm+dense layer0:
//   init (fused): cnt=0, map=INF, bitmap=0, rcount=0, rB=0
//   fill ELL(S):  8 edges/thread vector loads
//   map build:    map[bu[i]] = min batch index ; bitmap bit set
//   R chain:      row-stream-only vector loads -> bitmap test -> warp-scan
//                 compact (col/val fetched only for passing) -> vec4-red scatter
//   layer0 FUSED: warp gathers agg for 2 rows (ELL) then computes
//                 s2 = relu([agg,U]@W0+b0) in the same kernel (no s1 traffic)
//   aggB = (S@s2)[bu] ; gB = relu([aggB,s2[bu]]@W1+b1)   (batch)
//   out = [gB[slot]+rB[slot]; V[bp]; V[bn]]
// ---------------------------------------------------------------------------

#define D 64
#define NU 100000
#define BMAX 8192
#define DEGCAP 96
#define RCAP 1000000
#define XP 132                      // padded x row stride (floats)
#define NBMW ((NU + 31) / 32)

__device__ float g_s2[NU * D];
__device__ float g_aggB[BMAX * D];
__device__ float g_gB  [BMAX * D];
__device__ float g_rB  [BMAX * D];
__device__ int2  g_ellS[NU * DEGCAP];
__device__ int   g_cnt[NU];
__device__ int   g_map[NU];
__device__ unsigned g_bitmap[NBMW];
__device__ int4  g_cedge[RCAP];
__device__ int   g_rcount[1];

// ---------------------------------------------------------------------------
__global__ void init_kernel(int* __restrict__ cnt, int* __restrict__ map,
                            unsigned* __restrict__ bitmap,
                            float* __restrict__ rB, int* __restrict__ rcount,
                            int n_users, int b16) {
    int i = blockIdx.x * blockDim.x + threadIdx.x;
    if (i < n_users) { cnt[i] = 0; map[i] = 0x7FFFFFFF; }
    if (i < NBMW) bitmap[i] = 0u;
    if (i < b16) reinterpret_cast<float4*>(rB)[i] = make_float4(0.f, 0.f, 0.f, 0.f);
    if (i == 0) rcount[0] = 0;
}

// ELL build, 8 edges per thread.
__global__ void fill_ell_kernel(const int* __restrict__ row, const int* __restrict__ col,
                                const float* __restrict__ val, int nnz,
                                int* __restrict__ cnt, int2* __restrict__ ell) {
    int t = blockIdx.x * blockDim.x + threadIdx.x;
    int e0 = t * 8;
    if (e0 >= nnz) return;
    if (e0 + 7 < nnz) {
        int4   ra = __ldg(reinterpret_cast<const int4*>(row) + 2 * t);
        int4   rb = __ldg(reinterpret_cast<const int4*>(row) + 2 * t + 1);
        int4   ca = __ldg(reinterpret_cast<const int4*>(col) + 2 * t);
        int4   cb = __ldg(reinterpret_cast<const int4*>(col) + 2 * t + 1);
        float4 va = __ldg(reinterpret_cast<const float4*>(val) + 2 * t);
        float4 vb = __ldg(reinterpret_cast<const float4*>(val) + 2 * t + 1);
        int rr[8] = {ra.x, ra.y, ra.z, ra.w, rb.x, rb.y, rb.z, rb.w};
        int cc[8] = {ca.x, ca.y, ca.z, ca.w, cb.x, cb.y, cb.z, cb.w};
        float vv[8] = {va.x, va.y, va.z, va.w, vb.x, vb.y, vb.z, vb.w};
        #pragma unroll
        for (int k = 0; k < 8; k++) {
            int p = atomicAdd(cnt + rr[k], 1);
            if (p < DEGCAP)
                ell[rr[k] * DEGCAP + p] = make_int2(cc[k], __float_as_int(vv[k]));
        }
    } else {
        for (int e = e0; e < nnz; e++) {
            int r = __ldg(row + e);
            int p = atomicAdd(cnt + r, 1);
            if (p < DEGCAP)
                ell[r * DEGCAP + p] = make_int2(__ldg(col + e), __float_as_int(__ldg(val + e)));
        }
    }
}

__global__ void map_build_kernel(const int* __restrict__ bu, int B,
                                 int* __restrict__ map, unsigned* __restrict__ bitmap) {
    int i = blockIdx.x * blockDim.x + threadIdx.x;
    if (i >= B) return;
    int u = __ldg(bu + i);
    atomicMin(map + u, i);
    atomicOr(bitmap + (u >> 5), 1u << (u & 31));
}

// R compaction: vectorized ROW stream only; col/val fetched scalar for the
// ~8% passing edges. Bitmap test is L1-resident. Warp-scan rcount allocation.
__global__ void r_compact_kernel(const int* __restrict__ row, const int* __restrict__ col,
                                 const float* __restrict__ val, int nnz,
                                 const unsigned* __restrict__ bitmap,
                                 const int* __restrict__ map,
                                 int4* __restrict__ cedge, int* __restrict__ rcount) {
    int t = blockIdx.x * blockDim.x + threadIdx.x;
    int lane = threadIdx.x & 31;
    int e0 = t * 8;

    int rr[8];
    bool ps[8] = {false, false, false, false, false, false, false, false};
    int cnt_t = 0;

    if (e0 + 7 < nnz) {
        int4 ra = __ldg(reinterpret_cast<const int4*>(row) + 2 * t);
        int4 rb = __ldg(reinterpret_cast<const int4*>(row) + 2 * t + 1);
        rr[0] = ra.x; rr[1] = ra.y; rr[2] = ra.z; rr[3] = ra.w;
        rr[4] = rb.x; rr[5] = rb.y; rr[6] = rb.z; rr[7] = rb.w;
        #pragma unroll
        for (int k = 0; k < 8; k++) {
            ps[k] = (__ldg(bitmap + (rr[k] >> 5)) >> (rr[k] & 31)) & 1u;
            cnt_t += ps[k] ? 1 : 0;
        }
    } else if (e0 < nnz) {
        int m = nnz - e0;
        for (int k = 0; k < m; k++) {
            rr[k] = __ldg(row + e0 + k);
            ps[k] = (__ldg(bitmap + (rr[k] >> 5)) >> (rr[k] & 31)) & 1u;
            cnt_t += ps[k] ? 1 : 0;
        }
    }

    int pre = cnt_t;
    #pragma unroll
    for (int d = 1; d < 32; d <<= 1) {
        int v = __shfl_up_sync(0xFFFFFFFFu, pre, d);
        if (lane >= d) pre += v;
    }
    int total = __shfl_sync(0xFFFFFFFFu, pre, 31);
    if (total == 0) return;
    int base = 0;
    if (lane == 31) base = atomicAdd(rcount, total);
    base = __shfl_sync(0xFFFFFFFFu, base, 31);
    int p = base + pre - cnt_t;

    #pragma unroll
    for (int k = 0; k < 8; k++) {
        if (ps[k]) {
            if (p < RCAP) {
                int slot = __ldg(map + rr[k]);
                int c = __ldg(col + e0 + k);
                float v = __ldg(val + e0 + k);
                cedge[p] = make_int4(slot, c, __float_as_int(v), 0);
            }
            p++;
        }
    }
}

// Grid-stride, 16 threads per compact edge: rB[slot] += v * V[col].
__global__ void r_scatter_kernel(const int4* __restrict__ cedge,
                                 const int* __restrict__ rcount,
                                 const float* __restrict__ V,
                                 float* __restrict__ rB) {
    int n = min(__ldg(rcount), RCAP);
    long long total = (long long)n * 16;
    long long stride = (long long)gridDim.x * blockDim.x;
    for (long long idx = (long long)blockIdx.x * blockDim.x + threadIdx.x;
         idx < total; idx += stride) {
        int e    = (int)(idx >> 4);
        int lane = (int)(idx & 15);
        int4 ed = __ldg(cedge + e);
        float v = __int_as_float(ed.z);
        float4 x = *reinterpret_cast<const float4*>(V + (long long)ed.y * D + lane * 4);
        float* dst = rB + (long long)ed.x * D + lane * 4;
        asm volatile("red.global.add.v4.f32 [%0], {%1,%2,%3,%4};"
                     :: "l"(dst), "f"(v * x.x), "f"(v * x.y), "f"(v * x.z), "f"(v * x.w)
                     : "memory");
    }
}

// Per-row ELL gather helper: lane accumulates floats [2l, 2l+1].
__device__ __forceinline__ float2 gather_row(const int2* __restrict__ ep, int deg,
                                             const float* __restrict__ X, int lane) {
    float a0 = 0.f, a1 = 0.f;
    int j = 0;
    for (; j + 4 <= deg; j += 4) {
        int2 e0 = __ldg(ep + j);
        int2 e1 = __ldg(ep + j + 1);
        int2 e2 = __ldg(ep + j + 2);
        int2 e3 = __ldg(ep + j + 3);
        float2 x0 = *reinterpret_cast<const float2*>(X + (long long)e0.x * D + lane * 2);
        float2 x1 = *reinterpret_cast<const float2*>(X + (long long)e1.x * D + lane * 2);
        float2 x2 = *reinterpret_cast<const float2*>(X + (long long)e2.x * D + lane * 2);
        float2 x3 = *reinterpret_cast<const float2*>(X + (long long)e3.x * D + lane * 2);
        a0 = fmaf(__int_as_float(e0.y), x0.x, a0); a1 = fmaf(__int_as_float(e0.y), x0.y, a1);
        a0 = fmaf(__int_as_float(e1.y), x1.x, a0); a1 = fmaf(__int_as_float(e1.y), x1.y, a1);
        a0 = fmaf(__int_as_float(e2.y), x2.x, a0); a1 = fmaf(__int_as_float(e2.y), x2.y, a1);
        a0 = fmaf(__int_as_float(e3.y), x3.x, a0); a1 = fmaf(__int_as_float(e3.y), x3.y, a1);
    }
    for (; j < deg; j++) {
        int2 ee = __ldg(ep + j);
        float2 x = *reinterpret_cast<const float2*>(X + (long long)ee.x * D + lane * 2);
        float v = __int_as_float(ee.y);
        a0 = fmaf(v, x.x, a0); a1 = fmaf(v, x.y, a1);
    }
    return make_float2(a0, a1);
}

// FUSED layer0: per warp, gather agg for 2 rows (ELL) into per-warp smem x,
// append U rows, then dense 2 rows x (2 cols/lane): out = relu([agg,U]@W+b).
// Smem: Ws[128*64] | bs[64] | x[8 warps][2][XP].
__global__ __launch_bounds__(256)
void spmm_dense_kernel(const int* __restrict__ cnt, const int2* __restrict__ ell,
                       const float* __restrict__ U,
                       const float* __restrict__ W, const float* __restrict__ bvec,
                       float* __restrict__ out, int nrows) {
    extern __shared__ float sm[];
    float* Ws = sm;                    // 8192
    float* bs = sm + 8192;             // 64
    float* xs = sm + 8256;             // 8 * 2 * XP

    int tid = threadIdx.x;
    #pragma unroll
    for (int i = 0; i < 8; i++)
        reinterpret_cast<float4*>(Ws)[tid + i * 256] =
            reinterpret_cast<const float4*>(W)[tid + i * 256];
    if (tid < D) bs[tid] = bvec[tid];
    __syncthreads();

    int warp = tid >> 5, lane = tid & 31;
    float* x0 = xs + warp * 2 * XP;
    float* x1 = x0 + XP;

    for (int base = blockIdx.x * 16; base < nrows; base += gridDim.x * 16) {
        int r0 = base + warp * 2;
        if (r0 >= nrows) break;        // later strides only larger; warp-local exit ok
        int r1 = r0 + 1;
        bool has1 = (r1 < nrows);

        // Gather agg rows.
        float2 a0 = gather_row(ell + (long long)r0 * DEGCAP,
                               min(__ldg(cnt + r0), DEGCAP), U, lane);
        float2 a1 = make_float2(0.f, 0.f);
        if (has1)
            a1 = gather_row(ell + (long long)r1 * DEGCAP,
                            min(__ldg(cnt + r1), DEGCAP), U, lane);

        // Stage x = concat(agg, U[row]).
        x0[lane * 2]     = a0.x;
        x0[lane * 2 + 1] = a0.y;
        float2 u0 = *reinterpret_cast<const float2*>(U + (long long)r0 * D + lane * 2);
        x0[D + lane * 2]     = u0.x;
        x0[D + lane * 2 + 1] = u0.y;
        x1[lane * 2]     = a1.x;
        x1[lane * 2 + 1] = a1.y;
        float2 u1 = make_float2(0.f, 0.f);
        if (has1) u1 = *reinterpret_cast<const float2*>(U + (long long)r1 * D + lane * 2);
        x1[D + lane * 2]     = u1.x;
        x1[D + lane * 2 + 1] = u1.y;
        __syncwarp();

        // Dense: lane owns cols {2l, 2l+1}; 2 rows.
        float bx = bs[lane * 2], by = bs[lane * 2 + 1];
        float acc00 = bx, acc01 = by, acc10 = bx, acc11 = by;
        #pragma unroll 8
        for (int k = 0; k < 2 * D; k++) {
            float2 wv = *reinterpret_cast<const float2*>(&Ws[k * D + lane * 2]);
            float xv0 = x0[k], xv1 = x1[k];
            acc00 = fmaf(xv0, wv.x, acc00); acc01 = fmaf(xv0, wv.y, acc01);
            acc10 = fmaf(xv1, wv.x, acc10); acc11 = fmaf(xv1, wv.y, acc11);
        }
        acc00 = fmaxf(acc00, 0.f); acc01 = fmaxf(acc01, 0.f);
        acc10 = fmaxf(acc10, 0.f); acc11 = fmaxf(acc11, 0.f);
        *reinterpret_cast<float2*>(out + (long long)r0 * D + lane * 2) =
            make_float2(acc00, acc01);
        if (has1)
            *reinterpret_cast<float2*>(out + (long long)r1 * D + lane * 2) =
                make_float2(acc10, acc11);
        __syncwarp();
    }
}

// Warp-per-batch-index ELL gather (rows = bu[i]); skips duplicate batch slots.
__global__ __launch_bounds__(256)
void spmm_batch_kernel(const int* __restrict__ cnt, const int2* __restrict__ ell,
                       const float* __restrict__ X, const int* __restrict__ bu,
                       const int* __restrict__ map, float* __restrict__ Y, int B) {
    int gw   = (blockIdx.x * blockDim.x + threadIdx.x) >> 5;
    int lane = threadIdx.x & 31;
    if (gw >= B) return;
    int r = __ldg(bu + gw);
    if (__ldg(map + r) != gw) return;
    float2 a = gather_row(ell + (long long)r * DEGCAP,
                          min(__ldg(cnt + r), DEGCAP), X, lane);
    *reinterpret_cast<float2*>(Y + (long long)gw * D + lane * 2) = a;
}

// Dense layer (batch): out[r] = relu(concat(A[r], Uin[bu[r]]) @ W + b).
__global__ __launch_bounds__(256)
void dense_kernel(const float* __restrict__ A,
                  const float* __restrict__ Uin,
                  const int* __restrict__ bu,
                  const float* __restrict__ W,
                  const float* __restrict__ bvec,
                  float* __restrict__ out,
                  int nrows) {
    extern __shared__ float sm[];
    float* Ws = sm;                 // 8192 floats
    float* bs = sm + 8192;          // 64
    float* xs = sm + 8256;          // 64 * XP

    int tid = threadIdx.x;
    #pragma unroll
    for (int i = 0; i < 8; i++)
        reinterpret_cast<float4*>(Ws)[tid + i * 256] =
            reinterpret_cast<const float4*>(W)[tid + i * 256];
    if (tid < D) bs[tid] = bvec[tid];

    int base = blockIdx.x * 64;
    #pragma unroll
    for (int it = 0; it < 8; it++) {
        int s = it * 256 + tid;
        int r = s >> 5;
        int q = s & 31;
        int row = base + r;
        float4 v = make_float4(0.f, 0.f, 0.f, 0.f);
        if (row < nrows) {
            if (q < 16) {
                v = *reinterpret_cast<const float4*>(A + (long long)row * D + q * 4);
            } else {
                long long ur = bu ? (long long)__ldg(bu + row) : (long long)row;
                v = *reinterpret_cast<const float4*>(Uin + ur * D + (q - 16) * 4);
            }
        }
        *reinterpret_cast<float4*>(&xs[r * XP + q * 4]) = v;
    }
    __syncthreads();

    int cg = tid & 15;
    int rg = tid >> 4;
    const float* xr0 = &xs[(rg * 4 + 0) * XP];
    const float* xr1 = &xs[(rg * 4 + 1) * XP];
    const float* xr2 = &xs[(rg * 4 + 2) * XP];
    const float* xr3 = &xs[(rg * 4 + 3) * XP];

    float4 bv = *reinterpret_cast<const float4*>(&bs[cg * 4]);
    float4 a0 = bv, a1 = bv, a2 = bv, a3 = bv;

    #pragma unroll 4
    for (int k = 0; k < 2 * D; k++) {
        float4 w = *reinterpret_cast<const float4*>(&Ws[k * D + cg * 4]);
        float x0 = xr0[k], x1 = xr1[k], x2 = xr2[k], x3 = xr3[k];
        a0.x = fmaf(x0, w.x, a0.x); a0.y = fmaf(x0, w.y, a0.y);
        a0.z = fmaf(x0, w.z, a0.z); a0.w = fmaf(x0, w.w, a0.w);
        a1.x = fmaf(x1, w.x, a1.x); a1.y = fmaf(x1, w.y, a1.y);
        a1.z = fmaf(x1, w.z, a1.z); a1.w = fmaf(x1, w.w, a1.w);
        a2.x = fmaf(x2, w.x, a2.x); a2.y = fmaf(x2, w.y, a2.y);
        a2.z = fmaf(x2, w.z, a2.z); a2.w = fmaf(x2, w.w, a2.w);
        a3.x = fmaf(x3, w.x, a3.x); a3.y = fmaf(x3, w.y, a3.y);
        a3.z = fmaf(x3, w.z, a3.z); a3.w = fmaf(x3, w.w, a3.w);
    }

    float4 accs[4] = {a0, a1, a2, a3};
    #pragma unroll
    for (int rr = 0; rr < 4; rr++) {
        int row = base + rg * 4 + rr;
        if (row < nrows) {
            float4 a = accs[rr];
            a.x = fmaxf(a.x, 0.f); a.y = fmaxf(a.y, 0.f);
            a.z = fmaxf(a.z, 0.f); a.w = fmaxf(a.w, 0.f);
            *reinterpret_cast<float4*>(out + (long long)row * D + cg * 4) = a;
        }
    }
}

__global__ void gather_kernel(const int* __restrict__ bu,
                              const int* __restrict__ bp,
                              const int* __restrict__ bn,
                              const int* __restrict__ map,
                              const float* __restrict__ gB,
                              const float* __restrict__ rB,
                              const float* __restrict__ V,
                              float* __restrict__ out,
                              int B) {
    int i = blockIdx.x * blockDim.x + threadIdx.x;
    int total = 3 * B * 16;
    if (i >= total) return;
    int sec  = i / (B * 16);
    int rem  = i - sec * (B * 16);
    int r    = rem >> 4;
    int lane = rem & 15;
    float4 res;
    if (sec == 0) {
        long long slot = __ldg(map + __ldg(bu + r));
        float4 a = *reinterpret_cast<const float4*>(gB + slot * D + lane * 4);
        float4 bb = *reinterpret_cast<const float4*>(rB + slot * D + lane * 4);
        res = make_float4(a.x + bb.x, a.y + bb.y, a.z + bb.z, a.w + bb.w);
    } else if (sec == 1) {
        res = *reinterpret_cast<const float4*>(V + (long long)__ldg(bp + r) * D + lane * 4);
    } else {
        res = *reinterpret_cast<const float4*>(V + (long long)__ldg(bn + r) * D + lane * 4);
    }
    reinterpret_cast<float4*>(out)[i] = res;
}

// ---------------------------------------------------------------------------
extern "C" void kernel_launch(void* const* d_in, const int* in_sizes, int n_in,
                              void* d_out, int out_size) {
    const int*   bu    = (const int*)  d_in[0];
    const int*   bp    = (const int*)  d_in[1];
    const int*   bn    = (const int*)  d_in[2];
    const float* U     = (const float*)d_in[3];
    const float* V     = (const float*)d_in[4];
    const float* W0    = (const float*)d_in[5];
    const float* b0    = (const float*)d_in[6];
    const float* W1    = (const float*)d_in[7];
    const float* b1    = (const float*)d_in[8];
    const int*   S_row = (const int*)  d_in[9];
    const int*   S_col = (const int*)  d_in[10];
    const float* S_val = (const float*)d_in[11];
    const int*   R_row = (const int*)  d_in[12];
    const int*   R_col = (const int*)  d_in[13];
    const float* R_val = (const float*)d_in[14];

    int B       = in_sizes[0];
    int n_users = in_sizes[3] / D;
    int s_nnz   = in_sizes[9];
    int r_nnz   = in_sizes[12];

    float *s2, *aggB, *gB, *rB;
    int *cnt, *map, *rcount;
    unsigned *bitmap;
    int2 *ellS;
    int4 *cedge;
    cudaGetSymbolAddress((void**)&s2,     g_s2);
    cudaGetSymbolAddress((void**)&aggB,   g_aggB);
    cudaGetSymbolAddress((void**)&gB,     g_gB);
    cudaGetSymbolAddress((void**)&rB,     g_rB);
    cudaGetSymbolAddress((void**)&cnt,    g_cnt);
    cudaGetSymbolAddress((void**)&map,    g_map);
    cudaGetSymbolAddress((void**)&bitmap, g_bitmap);
    cudaGetSymbolAddress((void**)&rcount, g_rcount);
    cudaGetSymbolAddress((void**)&ellS,   g_ellS);
    cudaGetSymbolAddress((void**)&cedge,  g_cedge);

    const int DENSE_SMEM = (8192 + 64 + 64 * XP) * 4;           // 66816 B
    const int FUSED_SMEM = (8192 + 64 + 8 * 2 * XP) * 4;        // 41472 B
    static bool attr_done = false;
    if (!attr_done) {
        cudaFuncSetAttribute(dense_kernel,
                             cudaFuncAttributeMaxDynamicSharedMemorySize, DENSE_SMEM);
        cudaFuncSetAttribute(spmm_dense_kernel,
                             cudaFuncAttributeMaxDynamicSharedMemorySize, FUSED_SMEM);
        attr_done = true;
    }

    int b16 = B * 16;
    int init_n = (n_users > b16) ? n_users : b16;
    int st = (s_nnz + 7) / 8;
    int rt = (r_nnz + 7) / 8;
    int wb_batch = (B * 32 + 255) / 256;

    // --- init + ELL build + map + R chain ---
    init_kernel<<<(init_n + 255) / 256, 256>>>(cnt, map, bitmap, rB, rcount, n_users, b16);
    fill_ell_kernel<<<(st + 255) / 256, 256>>>(S_row, S_col, S_val, s_nnz, cnt, ellS);
    map_build_kernel<<<(B + 255) / 256, 256>>>(bu, B, map, bitmap);
    r_compact_kernel<<<(rt + 255) / 256, 256>>>(R_row, R_col, R_val, r_nnz, bitmap, map, cedge, rcount);
    r_scatter_kernel<<<2048, 256>>>(cedge, rcount, V, rB);

    // --- Layer 0: fused spmm + dense (grid-stride, ~4 blocks/SM) ---
    spmm_dense_kernel<<<592, 256, FUSED_SMEM>>>(cnt, ellS, U, W0, b0, s2, n_users);

    // --- Layer 1 (batch rows only) ---
    spmm_batch_kernel<<<wb_batch, 256>>>(cnt, ellS, s2, bu, map, aggB, B);
    dense_kernel<<<(B + 63) / 64, 256, DENSE_SMEM>>>(aggB, s2, bu, W1, b1, gB, B);

    // --- Gather outputs ---
    int g_total = 3 * B * 16;
    gather_kernel<<<(g_total + 255) / 256, 256>>>(bu, bp, bn, map, gB, rB, V, (float*)d_out, B);
}

// round 14
// speedup vs baseline: 1.0345x; 1.0345x over previous
#include <cuda_runtime.h>
#include <cuda_bf16.h>
#include <cstdint>

// ---------------------------------------------------------------------------
// DiffNet forward, batch-sparsified, ELL layout, split kernels (R12 struct):
//   init: cnt=0, map=INF, bitmap=0, rcount=0, rB=0
//   fill ELL(S):  16 edges/thread vector loads
//   map build:    map[bu[i]] = min batch index ; bitmap bit set
//   R chain:      16 edges/thread row-stream -> bitmap test -> warp-scan
//                 compact (col/val fetched only for passing) -> vec4-red scatter
//   s1 = S@U ; s2 = relu([s1,U]@W0+b0)          (full, ELL gather, 8-unroll)
//   aggB = (S@s2)[bu] ; gB = relu([aggB,s2[bu]]@W1+b1)   (batch)
//   out = [gB[slot]+rB[slot]; V[bp]; V[bn]]
// ---------------------------------------------------------------------------

#define D 64
#define NU 100000
#define BMAX 8192
#define DEGCAP 96
#define RCAP 1000000
#define XP 132
#define NBMW ((NU + 31) / 32)

__device__ float g_s1[NU * D];
__device__ float g_s2[NU * D];
__device__ float g_aggB[BMAX * D];
__device__ float g_gB  [BMAX * D];
__device__ float g_rB  [BMAX * D];
__device__ int2  g_ellS[NU * DEGCAP];
__device__ int   g_cnt[NU];
__device__ int   g_map[NU];
__device__ unsigned g_bitmap[NBMW];
__device__ int4  g_cedge[RCAP];
__device__ int   g_rcount[1];

// ---------------------------------------------------------------------------
__global__ void init_kernel(int* __restrict__ cnt, int* __restrict__ map,
                            unsigned* __restrict__ bitmap,
                            float* __restrict__ rB, int* __restrict__ rcount,
                            int n_users, int b16) {
    int i = blockIdx.x * blockDim.x + threadIdx.x;
    if (i < n_users) { cnt[i] = 0; map[i] = 0x7FFFFFFF; }
    if (i < NBMW) bitmap[i] = 0u;
    if (i < b16) reinterpret_cast<float4*>(rB)[i] = make_float4(0.f, 0.f, 0.f, 0.f);
    if (i == 0) rcount[0] = 0;
}

// ELL build, 16 edges per thread (4x vector loads per stream).
__global__ void fill_ell_kernel(const int* __restrict__ row, const int* __restrict__ col,
                                const float* __restrict__ val, int nnz,
                                int* __restrict__ cnt, int2* __restrict__ ell) {
    int t = blockIdx.x * blockDim.x + threadIdx.x;
    int e0 = t * 16;
    if (e0 >= nnz) return;
    if (e0 + 15 < nnz) {
        int rr[16], cc[16];
        float vv[16];
        #pragma unroll
        for (int q = 0; q < 4; q++) {
            int4   r4 = __ldg(reinterpret_cast<const int4*>(row) + 4 * t + q);
            int4   c4 = __ldg(reinterpret_cast<const int4*>(col) + 4 * t + q);
            float4 v4 = __ldg(reinterpret_cast<const float4*>(val) + 4 * t + q);
            rr[q*4+0] = r4.x; rr[q*4+1] = r4.y; rr[q*4+2] = r4.z; rr[q*4+3] = r4.w;
            cc[q*4+0] = c4.x; cc[q*4+1] = c4.y; cc[q*4+2] = c4.z; cc[q*4+3] = c4.w;
            vv[q*4+0] = v4.x; vv[q*4+1] = v4.y; vv[q*4+2] = v4.z; vv[q*4+3] = v4.w;
        }
        #pragma unroll
        for (int k = 0; k < 16; k++) {
            int p = atomicAdd(cnt + rr[k], 1);
            if (p < DEGCAP)
                ell[rr[k] * DEGCAP + p] = make_int2(cc[k], __float_as_int(vv[k]));
        }
    } else {
        for (int e = e0; e < nnz; e++) {
            int r = __ldg(row + e);
            int p = atomicAdd(cnt + r, 1);
            if (p < DEGCAP)
                ell[r * DEGCAP + p] = make_int2(__ldg(col + e), __float_as_int(__ldg(val + e)));
        }
    }
}

__global__ void map_build_kernel(const int* __restrict__ bu, int B,
                                 int* __restrict__ map, unsigned* __restrict__ bitmap) {
    int i = blockIdx.x * blockDim.x + threadIdx.x;
    if (i >= B) return;
    int u = __ldg(bu + i);
    atomicMin(map + u, i);
    atomicOr(bitmap + (u >> 5), 1u << (u & 31));
}

// R compaction, 16 edges/thread: vectorized ROW stream; col/val fetched scalar
// for the ~8% passing edges. Bitmap test L1-resident; warp-scan allocation.
__global__ void r_compact_kernel(const int* __restrict__ row, const int* __restrict__ col,
                                 const float* __restrict__ val, int nnz,
                                 const unsigned* __restrict__ bitmap,
                                 const int* __restrict__ map,
                                 int4* __restrict__ cedge, int* __restrict__ rcount) {
    int t = blockIdx.x * blockDim.x + threadIdx.x;
    int lane = threadIdx.x & 31;
    int e0 = t * 16;

    int rr[16];
    unsigned pmask = 0;
    int cnt_t = 0;

    if (e0 + 15 < nnz) {
        #pragma unroll
        for (int q = 0; q < 4; q++) {
            int4 r4 = __ldg(reinterpret_cast<const int4*>(row) + 4 * t + q);
            rr[q*4+0] = r4.x; rr[q*4+1] = r4.y; rr[q*4+2] = r4.z; rr[q*4+3] = r4.w;
        }
        #pragma unroll
        for (int k = 0; k < 16; k++) {
            bool p = (__ldg(bitmap + (rr[k] >> 5)) >> (rr[k] & 31)) & 1u;
            pmask |= p ? (1u << k) : 0u;
            cnt_t += p ? 1 : 0;
        }
    } else if (e0 < nnz) {
        int m = nnz - e0;
        for (int k = 0; k < m; k++) {
            rr[k] = __ldg(row + e0 + k);
            bool p = (__ldg(bitmap + (rr[k] >> 5)) >> (rr[k] & 31)) & 1u;
            pmask |= p ? (1u << k) : 0u;
            cnt_t += p ? 1 : 0;
        }
    }

    int pre = cnt_t;
    #pragma unroll
    for (int d = 1; d < 32; d <<= 1) {
        int v = __shfl_up_sync(0xFFFFFFFFu, pre, d);
        if (lane >= d) pre += v;
    }
    int total = __shfl_sync(0xFFFFFFFFu, pre, 31);
    if (total == 0) return;
    int base = 0;
    if (lane == 31) base = atomicAdd(rcount, total);
    base = __shfl_sync(0xFFFFFFFFu, base, 31);
    int p = base + pre - cnt_t;

    #pragma unroll
    for (int k = 0; k < 16; k++) {
        if (pmask & (1u << k)) {
            if (p < RCAP) {
                int slot = __ldg(map + rr[k]);
                int c = __ldg(col + e0 + k);
                float v = __ldg(val + e0 + k);
                cedge[p] = make_int4(slot, c, __float_as_int(v), 0);
            }
            p++;
        }
    }
}

// Grid-stride, 16 threads per compact edge: rB[slot] += v * V[col].
__global__ void r_scatter_kernel(const int4* __restrict__ cedge,
                                 const int* __restrict__ rcount,
                                 const float* __restrict__ V,
                                 float* __restrict__ rB) {
    int n = min(__ldg(rcount), RCAP);
    long long total = (long long)n * 16;
    long long stride = (long long)gridDim.x * blockDim.x;
    for (long long idx = (long long)blockIdx.x * blockDim.x + threadIdx.x;
         idx < total; idx += stride) {
        int e    = (int)(idx >> 4);
        int lane = (int)(idx & 15);
        int4 ed = __ldg(cedge + e);
        float v = __int_as_float(ed.z);
        float4 x = *reinterpret_cast<const float4*>(V + (long long)ed.y * D + lane * 4);
        float* dst = rB + (long long)ed.x * D + lane * 4;
        asm volatile("red.global.add.v4.f32 [%0], {%1,%2,%3,%4};"
                     :: "l"(dst), "f"(v * x.x), "f"(v * x.y), "f"(v * x.z), "f"(v * x.w)
                     : "memory");
    }
}

// Warp-per-row ELL gather spmm over ALL rows; 8-edge unroll for MLP.
__global__ __launch_bounds__(256)
void spmm_full_kernel(const int* __restrict__ cnt, const int2* __restrict__ ell,
                      const float* __restrict__ X, float* __restrict__ Y, int nrows) {
    int gw   = (blockIdx.x * blockDim.x + threadIdx.x) >> 5;
    int lane = threadIdx.x & 31;
    if (gw >= nrows) return;
    int deg = min(__ldg(cnt + gw), DEGCAP);
    const int2* ep = ell + (long long)gw * DEGCAP;
    float a0 = 0.f, a1 = 0.f;
    int j = 0;
    for (; j + 8 <= deg; j += 8) {
        int2 e0 = __ldg(ep + j);
        int2 e1 = __ldg(ep + j + 1);
        int2 e2 = __ldg(ep + j + 2);
        int2 e3 = __ldg(ep + j + 3);
        int2 e4 = __ldg(ep + j + 4);
        int2 e5 = __ldg(ep + j + 5);
        int2 e6 = __ldg(ep + j + 6);
        int2 e7 = __ldg(ep + j + 7);
        float2 x0 = *reinterpret_cast<const float2*>(X + (long long)e0.x * D + lane * 2);
        float2 x1 = *reinterpret_cast<const float2*>(X + (long long)e1.x * D + lane * 2);
        float2 x2 = *reinterpret_cast<const float2*>(X + (long long)e2.x * D + lane * 2);
        float2 x3 = *reinterpret_cast<const float2*>(X + (long long)e3.x * D + lane * 2);
        float2 x4 = *reinterpret_cast<const float2*>(X + (long long)e4.x * D + lane * 2);
        float2 x5 = *reinterpret_cast<const float2*>(X + (long long)e5.x * D + lane * 2);
        float2 x6 = *reinterpret_cast<const float2*>(X + (long long)e6.x * D + lane * 2);
        float2 x7 = *reinterpret_cast<const float2*>(X + (long long)e7.x * D + lane * 2);
        a0 = fmaf(__int_as_float(e0.y), x0.x, a0); a1 = fmaf(__int_as_float(e0.y), x0.y, a1);
        a0 = fmaf(__int_as_float(e1.y), x1.x, a0); a1 = fmaf(__int_as_float(e1.y), x1.y, a1);
        a0 = fmaf(__int_as_float(e2.y), x2.x, a0); a1 = fmaf(__int_as_float(e2.y), x2.y, a1);
        a0 = fmaf(__int_as_float(e3.y), x3.x, a0); a1 = fmaf(__int_as_float(e3.y), x3.y, a1);
        a0 = fmaf(__int_as_float(e4.y), x4.x, a0); a1 = fmaf(__int_as_float(e4.y), x4.y, a1);
        a0 = fmaf(__int_as_float(e5.y), x5.x, a0); a1 = fmaf(__int_as_float(e5.y), x5.y, a1);
        a0 = fmaf(__int_as_float(e6.y), x6.x, a0); a1 = fmaf(__int_as_float(e6.y), x6.y, a1);
        a0 = fmaf(__int_as_float(e7.y), x7.x, a0); a1 = fmaf(__int_as_float(e7.y), x7.y, a1);
    }
    for (; j < deg; j++) {
        int2 ee = __ldg(ep + j);
        float2 x = *reinterpret_cast<const float2*>(X + (long long)ee.x * D + lane * 2);
        float v = __int_as_float(ee.y);
        a0 = fmaf(v, x.x, a0); a1 = fmaf(v, x.y, a1);
    }
    *reinterpret_cast<float2*>(Y + (long long)gw * D + lane * 2) = make_float2(a0, a1);
}

// Warp-per-batch-index ELL gather (rows = bu[i]); skips duplicate batch slots.
__global__ __launch_bounds__(256)
void spmm_batch_kernel(const int* __restrict__ cnt, const int2* __restrict__ ell,
                       const float* __restrict__ X, const int* __restrict__ bu,
                       const int* __restrict__ map, float* __restrict__ Y, int B) {
    int gw   = (blockIdx.x * blockDim.x + threadIdx.x) >> 5;
    int lane = threadIdx.x & 31;
    if (gw >= B) return;
    int r = __ldg(bu + gw);
    if (__ldg(map + r) != gw) return;
    int deg = min(__ldg(cnt + r), DEGCAP);
    const int2* ep = ell + (long long)r * DEGCAP;
    float a0 = 0.f, a1 = 0.f;
    int j = 0;
    for (; j + 4 <= deg; j += 4) {
        int2 e0 = __ldg(ep + j);
        int2 e1 = __ldg(ep + j + 1);
        int2 e2 = __ldg(ep + j + 2);
        int2 e3 = __ldg(ep + j + 3);
        float2 x0 = *reinterpret_cast<const float2*>(X + (long long)e0.x * D + lane * 2);
        float2 x1 = *reinterpret_cast<const float2*>(X + (long long)e1.x * D + lane * 2);
        float2 x2 = *reinterpret_cast<const float2*>(X + (long long)e2.x * D + lane * 2);
        float2 x3 = *reinterpret_cast<const float2*>(X + (long long)e3.x * D + lane * 2);
        a0 = fmaf(__int_as_float(e0.y), x0.x, a0); a1 = fmaf(__int_as_float(e0.y), x0.y, a1);
        a0 = fmaf(__int_as_float(e1.y), x1.x, a0); a1 = fmaf(__int_as_float(e1.y), x1.y, a1);
        a0 = fmaf(__int_as_float(e2.y), x2.x, a0); a1 = fmaf(__int_as_float(e2.y), x2.y, a1);
        a0 = fmaf(__int_as_float(e3.y), x3.x, a0); a1 = fmaf(__int_as_float(e3.y), x3.y, a1);
    }
    for (; j < deg; j++) {
        int2 ee = __ldg(ep + j);
        float2 x = *reinterpret_cast<const float2*>(X + (long long)ee.x * D + lane * 2);
        float v = __int_as_float(ee.y);
        a0 = fmaf(v, x.x, a0); a1 = fmaf(v, x.y, a1);
    }
    *reinterpret_cast<float2*>(Y + (long long)gw * D + lane * 2) = make_float2(a0, a1);
}

// Dense layer: out[r] = relu(concat(A[r], Uin[urow]) @ W + b).
// 64-row tile per block; thread = (rg, cg): 4 rows x 4 cols, 16 accumulators.
__global__ __launch_bounds__(256)
void dense_kernel(const float* __restrict__ A,
                  const float* __restrict__ Uin,
                  const int* __restrict__ bu,
                  const float* __restrict__ W,
                  const float* __restrict__ bvec,
                  float* __restrict__ out,
                  int nrows) {
    extern __shared__ float sm[];
    float* Ws = sm;                 // 8192 floats
    float* bs = sm + 8192;          // 64
    float* xs = sm + 8256;          // 64 * XP

    int tid = threadIdx.x;
    #pragma unroll
    for (int i = 0; i < 8; i++)
        reinterpret_cast<float4*>(Ws)[tid + i * 256] =
            reinterpret_cast<const float4*>(W)[tid + i * 256];
    if (tid < D) bs[tid] = bvec[tid];

    int base = blockIdx.x * 64;
    #pragma unroll
    for (int it = 0; it < 8; it++) {
        int s = it * 256 + tid;
        int r = s >> 5;
        int q = s & 31;
        int row = base + r;
        float4 v = make_float4(0.f, 0.f, 0.f, 0.f);
        if (row < nrows) {
            if (q < 16) {
                v = *reinterpret_cast<const float4*>(A + (long long)row * D + q * 4);
            } else {
                long long ur = bu ? (long long)__ldg(bu + row) : (long long)row;
                v = *reinterpret_cast<const float4*>(Uin + ur * D + (q - 16) * 4);
            }
        }
        *reinterpret_cast<float4*>(&xs[r * XP + q * 4]) = v;
    }
    __syncthreads();

    int cg = tid & 15;
    int rg = tid >> 4;
    const float* xr0 = &xs[(rg * 4 + 0) * XP];
    const float* xr1 = &xs[(rg * 4 + 1) * XP];
    const float* xr2 = &xs[(rg * 4 + 2) * XP];
    const float* xr3 = &xs[(rg * 4 + 3) * XP];

    float4 bv = *reinterpret_cast<const float4*>(&bs[cg * 4]);
    float4 a0 = bv, a1 = bv, a2 = bv, a3 = bv;

    #pragma unroll 4
    for (int k = 0; k < 2 * D; k++) {
        float4 w = *reinterpret_cast<const float4*>(&Ws[k * D + cg * 4]);
        float x0 = xr0[k], x1 = xr1[k], x2 = xr2[k], x3 = xr3[k];
        a0.x = fmaf(x0, w.x, a0.x); a0.y = fmaf(x0, w.y, a0.y);
        a0.z = fmaf(x0, w.z, a0.z); a0.w = fmaf(x0, w.w, a0.w);
        a1.x = fmaf(x1, w.x, a1.x); a1.y = fmaf(x1, w.y, a1.y);
        a1.z = fmaf(x1, w.z, a1.z); a1.w = fmaf(x1, w.w, a1.w);
        a2.x = fmaf(x2, w.x, a2.x); a2.y = fmaf(x2, w.y, a2.y);
        a2.z = fmaf(x2, w.z, a2.z); a2.w = fmaf(x2, w.w, a2.w);
        a3.x = fmaf(x3, w.x, a3.x); a3.y = fmaf(x3, w.y, a3.y);
        a3.z = fmaf(x3, w.z, a3.z); a3.w = fmaf(x3, w.w, a3.w);
    }

    float4 accs[4] = {a0, a1, a2, a3};
    #pragma unroll
    for (int rr = 0; rr < 4; rr++) {
        int row = base + rg * 4 + rr;
        if (row < nrows) {
            float4 a = accs[rr];
            a.x = fmaxf(a.x, 0.f); a.y = fmaxf(a.y, 0.f);
            a.z = fmaxf(a.z, 0.f); a.w = fmaxf(a.w, 0.f);
            *reinterpret_cast<float4*>(out + (long long)row * D + cg * 4) = a;
        }
    }
}

__global__ void gather_kernel(const int* __restrict__ bu,
                              const int* __restrict__ bp,
                              const int* __restrict__ bn,
                              const int* __restrict__ map,
                              const float* __restrict__ gB,
                              const float* __restrict__ rB,
                              const float* __restrict__ V,
                              float* __restrict__ out,
                              int B) {
    int i = blockIdx.x * blockDim.x + threadIdx.x;
    int total = 3 * B * 16;
    if (i >= total) return;
    int sec  = i / (B * 16);
    int rem  = i - sec * (B * 16);
    int r    = rem >> 4;
    int lane = rem & 15;
    float4 res;
    if (sec == 0) {
        long long slot = __ldg(map + __ldg(bu + r));
        float4 a = *reinterpret_cast<const float4*>(gB + slot * D + lane * 4);
        float4 bb = *reinterpret_cast<const float4*>(rB + slot * D + lane * 4);
        res = make_float4(a.x + bb.x, a.y + bb.y, a.z + bb.z, a.w + bb.w);
    } else if (sec == 1) {
        res = *reinterpret_cast<const float4*>(V + (long long)__ldg(bp + r) * D + lane * 4);
    } else {
        res = *reinterpret_cast<const float4*>(V + (long long)__ldg(bn + r) * D + lane * 4);
    }
    reinterpret_cast<float4*>(out)[i] = res;
}

// ---------------------------------------------------------------------------
extern "C" void kernel_launch(void* const* d_in, const int* in_sizes, int n_in,
                              void* d_out, int out_size) {
    const int*   bu    = (const int*)  d_in[0];
    const int*   bp    = (const int*)  d_in[1];
    const int*   bn    = (const int*)  d_in[2];
    const float* U     = (const float*)d_in[3];
    const float* V     = (const float*)d_in[4];
    const float* W0    = (const float*)d_in[5];
    const float* b0    = (const float*)d_in[6];
    const float* W1    = (const float*)d_in[7];
    const float* b1    = (const float*)d_in[8];
    const int*   S_row = (const int*)  d_in[9];
    const int*   S_col = (const int*)  d_in[10];
    const float* S_val = (const float*)d_in[11];
    const int*   R_row = (const int*)  d_in[12];
    const int*   R_col = (const int*)  d_in[13];
    const float* R_val = (const float*)d_in[14];

    int B       = in_sizes[0];
    int n_users = in_sizes[3] / D;
    int s_nnz   = in_sizes[9];
    int r_nnz   = in_sizes[12];

    float *s1, *s2, *aggB, *gB, *rB;
    int *cnt, *map, *rcount;
    unsigned *bitmap;
    int2 *ellS;
    int4 *cedge;
    cudaGetSymbolAddress((void**)&s1,     g_s1);
    cudaGetSymbolAddress((void**)&s2,     g_s2);
    cudaGetSymbolAddress((void**)&aggB,   g_aggB);
    cudaGetSymbolAddress((void**)&gB,     g_gB);
    cudaGetSymbolAddress((void**)&rB,     g_rB);
    cudaGetSymbolAddress((void**)&cnt,    g_cnt);
    cudaGetSymbolAddress((void**)&map,    g_map);
    cudaGetSymbolAddress((void**)&bitmap, g_bitmap);
    cudaGetSymbolAddress((void**)&rcount, g_rcount);
    cudaGetSymbolAddress((void**)&ellS,   g_ellS);
    cudaGetSymbolAddress((void**)&cedge,  g_cedge);

    const int DENSE_SMEM = (8192 + 64 + 64 * XP) * 4;   // 66816 bytes
    static bool attr_done = false;
    if (!attr_done) {
        cudaFuncSetAttribute(dense_kernel,
                             cudaFuncAttributeMaxDynamicSharedMemorySize, DENSE_SMEM);
        attr_done = true;
    }

    int b16 = B * 16;
    int init_n = (n_users > b16) ? n_users : b16;
    int st = (s_nnz + 15) / 16;             // 16 edges per thread
    int rt = (r_nnz + 15) / 16;
    int wb_full  = (n_users * 32 + 255) / 256;
    int wb_batch = (B * 32 + 255) / 256;

    // --- init + ELL build + map + R chain ---
    init_kernel<<<(init_n + 255) / 256, 256>>>(cnt, map, bitmap, rB, rcount, n_users, b16);
    fill_ell_kernel<<<(st + 255) / 256, 256>>>(S_row, S_col, S_val, s_nnz, cnt, ellS);
    map_build_kernel<<<(B + 255) / 256, 256>>>(bu, B, map, bitmap);
    r_compact_kernel<<<(rt + 255) / 256, 256>>>(R_row, R_col, R_val, r_nnz, bitmap, map, cedge, rcount);
    r_scatter_kernel<<<2048, 256>>>(cedge, rcount, V, rB);

    // --- Layer 0 (full, split spmm + dense) ---
    spmm_full_kernel<<<wb_full, 256>>>(cnt, ellS, U, s1, n_users);
    dense_kernel<<<(n_users + 63) / 64, 256, DENSE_SMEM>>>(s1, U, nullptr, W0, b0, s2, n_users);

    // --- Layer 1 (batch rows only) ---
    spmm_batch_kernel<<<wb_batch, 256>>>(cnt, ellS, s2, bu, map, aggB, B);
    dense_kernel<<<(B + 63) / 64, 256, DENSE_SMEM>>>(aggB, s2, bu, W1, b1, gB, B);

    // --- Gather outputs ---
    int g_total = 3 * B * 16;
    gather_kernel<<<(g_total + 255) / 256, 256>>>(bu, bp, bn, map, gB, rB, V, (float*)d_out, B);
}

// round 16
// speedup vs baseline: 1.1737x; 1.1346x over previous
#include <cuda_runtime.h>
#include <cuda_bf16.h>
#include <cstdint>

// ---------------------------------------------------------------------------
// DiffNet forward, batch-sparsified, ELL layout, 2-stream overlap (lean R):
//   A: init -> fill ELL(S,8/thr) -> spmm_full -> dense0
//   B: (after init) map build -> r_compact(16/thr) -> r_scatter
//   A: (wait map) spmm_batch -> dense_b -> (wait R) gather
// ---------------------------------------------------------------------------

#define D 64
#define NU 100000
#define BMAX 8192
#define DEGCAP 96
#define RCAP 1000000
#define XP 132
#define NBMW ((NU + 31) / 32)

__device__ float g_s1[NU * D];
__device__ float g_s2[NU * D];
__device__ float g_aggB[BMAX * D];
__device__ float g_gB  [BMAX * D];
__device__ float g_rB  [BMAX * D];
__device__ int2  g_ellS[NU * DEGCAP];
__device__ int   g_cnt[NU];
__device__ int   g_map[NU];
__device__ unsigned g_bitmap[NBMW];
__device__ int4  g_cedge[RCAP];
__device__ int   g_rcount[1];

// ---------------------------------------------------------------------------
__global__ void init_kernel(int* __restrict__ cnt, int* __restrict__ map,
                            unsigned* __restrict__ bitmap,
                            float* __restrict__ rB, int* __restrict__ rcount,
                            int n_users, int b16) {
    int i = blockIdx.x * blockDim.x + threadIdx.x;
    if (i < n_users) { cnt[i] = 0; map[i] = 0x7FFFFFFF; }
    if (i < NBMW) bitmap[i] = 0u;
    if (i < b16) reinterpret_cast<float4*>(rB)[i] = make_float4(0.f, 0.f, 0.f, 0.f);
    if (i == 0) rcount[0] = 0;
}

// ELL build, 8 edges per thread (best measured shape).
__global__ void fill_ell_kernel(const int* __restrict__ row, const int* __restrict__ col,
                                const float* __restrict__ val, int nnz,
                                int* __restrict__ cnt, int2* __restrict__ ell) {
    int t = blockIdx.x * blockDim.x + threadIdx.x;
    int e0 = t * 8;
    if (e0 >= nnz) return;
    if (e0 + 7 < nnz) {
        int4   ra = __ldg(reinterpret_cast<const int4*>(row) + 2 * t);
        int4   rb = __ldg(reinterpret_cast<const int4*>(row) + 2 * t + 1);
        int4   ca = __ldg(reinterpret_cast<const int4*>(col) + 2 * t);
        int4   cb = __ldg(reinterpret_cast<const int4*>(col) + 2 * t + 1);
        float4 va = __ldg(reinterpret_cast<const float4*>(val) + 2 * t);
        float4 vb = __ldg(reinterpret_cast<const float4*>(val) + 2 * t + 1);
        int rr[8] = {ra.x, ra.y, ra.z, ra.w, rb.x, rb.y, rb.z, rb.w};
        int cc[8] = {ca.x, ca.y, ca.z, ca.w, cb.x, cb.y, cb.z, cb.w};
        float vv[8] = {va.x, va.y, va.z, va.w, vb.x, vb.y, vb.z, vb.w};
        #pragma unroll
        for (int k = 0; k < 8; k++) {
            int p = atomicAdd(cnt + rr[k], 1);
            if (p < DEGCAP)
                ell[rr[k] * DEGCAP + p] = make_int2(cc[k], __float_as_int(vv[k]));
        }
    } else {
        for (int e = e0; e < nnz; e++) {
            int r = __ldg(row + e);
            int p = atomicAdd(cnt + r, 1);
            if (p < DEGCAP)
                ell[r * DEGCAP + p] = make_int2(__ldg(col + e), __float_as_int(__ldg(val + e)));
        }
    }
}

__global__ void map_build_kernel(const int* __restrict__ bu, int B,
                                 int* __restrict__ map, unsigned* __restrict__ bitmap) {
    int i = blockIdx.x * blockDim.x + threadIdx.x;
    if (i >= B) return;
    int u = __ldg(bu + i);
    atomicMin(map + u, i);
    atomicOr(bitmap + (u >> 5), 1u << (u & 31));
}

// R compaction, 16 edges/thread: vectorized ROW stream; col/val fetched only
// for passing edges. Bitmap test L1-resident; warp-scan allocation.
__global__ void r_compact_kernel(const int* __restrict__ row, const int* __restrict__ col,
                                 const float* __restrict__ val, int nnz,
                                 const unsigned* __restrict__ bitmap,
                                 const int* __restrict__ map,
                                 int4* __restrict__ cedge, int* __restrict__ rcount) {
    int t = blockIdx.x * blockDim.x + threadIdx.x;
    int lane = threadIdx.x & 31;
    int e0 = t * 16;

    int rr[16];
    unsigned pmask = 0;
    int cnt_t = 0;

    if (e0 + 15 < nnz) {
        #pragma unroll
        for (int q = 0; q < 4; q++) {
            int4 r4 = __ldg(reinterpret_cast<const int4*>(row) + 4 * t + q);
            rr[q*4+0] = r4.x; rr[q*4+1] = r4.y; rr[q*4+2] = r4.z; rr[q*4+3] = r4.w;
        }
        #pragma unroll
        for (int k = 0; k < 16; k++) {
            bool p = (__ldg(bitmap + (rr[k] >> 5)) >> (rr[k] & 31)) & 1u;
            pmask |= p ? (1u << k) : 0u;
            cnt_t += p ? 1 : 0;
        }
    } else if (e0 < nnz) {
        int m = nnz - e0;
        for (int k = 0; k < m; k++) {
            rr[k] = __ldg(row + e0 + k);
            bool p = (__ldg(bitmap + (rr[k] >> 5)) >> (rr[k] & 31)) & 1u;
            pmask |= p ? (1u << k) : 0u;
            cnt_t += p ? 1 : 0;
        }
    }

    int pre = cnt_t;
    #pragma unroll
    for (int d = 1; d < 32; d <<= 1) {
        int v = __shfl_up_sync(0xFFFFFFFFu, pre, d);
        if (lane >= d) pre += v;
    }
    int total = __shfl_sync(0xFFFFFFFFu, pre, 31);
    if (total == 0) return;
    int base = 0;
    if (lane == 31) base = atomicAdd(rcount, total);
    base = __shfl_sync(0xFFFFFFFFu, base, 31);
    int p = base + pre - cnt_t;

    #pragma unroll
    for (int k = 0; k < 16; k++) {
        if (pmask & (1u << k)) {
            if (p < RCAP) {
                int slot = __ldg(map + rr[k]);
                int c = __ldg(col + e0 + k);
                float v = __ldg(val + e0 + k);
                cedge[p] = make_int4(slot, c, __float_as_int(v), 0);
            }
            p++;
        }
    }
}

// Grid-stride, 16 threads per compact edge: rB[slot] += v * V[col].
__global__ void r_scatter_kernel(const int4* __restrict__ cedge,
                                 const int* __restrict__ rcount,
                                 const float* __restrict__ V,
                                 float* __restrict__ rB) {
    int n = min(__ldg(rcount), RCAP);
    long long total = (long long)n * 16;
    long long stride = (long long)gridDim.x * blockDim.x;
    for (long long idx = (long long)blockIdx.x * blockDim.x + threadIdx.x;
         idx < total; idx += stride) {
        int e    = (int)(idx >> 4);
        int lane = (int)(idx & 15);
        int4 ed = __ldg(cedge + e);
        float v = __int_as_float(ed.z);
        float4 x = *reinterpret_cast<const float4*>(V + (long long)ed.y * D + lane * 4);
        float* dst = rB + (long long)ed.x * D + lane * 4;
        asm volatile("red.global.add.v4.f32 [%0], {%1,%2,%3,%4};"
                     :: "l"(dst), "f"(v * x.x), "f"(v * x.y), "f"(v * x.z), "f"(v * x.w)
                     : "memory");
    }
}

// Warp-per-row ELL gather spmm over ALL rows; 8-edge unroll for MLP.
__global__ __launch_bounds__(256)
void spmm_full_kernel(const int* __restrict__ cnt, const int2* __restrict__ ell,
                      const float* __restrict__ X, float* __restrict__ Y, int nrows) {
    int gw   = (blockIdx.x * blockDim.x + threadIdx.x) >> 5;
    int lane = threadIdx.x & 31;
    if (gw >= nrows) return;
    int deg = min(__ldg(cnt + gw), DEGCAP);
    const int2* ep = ell + (long long)gw * DEGCAP;
    float a0 = 0.f, a1 = 0.f;
    int j = 0;
    for (; j + 8 <= deg; j += 8) {
        int2 e0 = __ldg(ep + j);
        int2 e1 = __ldg(ep + j + 1);
        int2 e2 = __ldg(ep + j + 2);
        int2 e3 = __ldg(ep + j + 3);
        int2 e4 = __ldg(ep + j + 4);
        int2 e5 = __ldg(ep + j + 5);
        int2 e6 = __ldg(ep + j + 6);
        int2 e7 = __ldg(ep + j + 7);
        float2 x0 = *reinterpret_cast<const float2*>(X + (long long)e0.x * D + lane * 2);
        float2 x1 = *reinterpret_cast<const float2*>(X + (long long)e1.x * D + lane * 2);
        float2 x2 = *reinterpret_cast<const float2*>(X + (long long)e2.x * D + lane * 2);
        float2 x3 = *reinterpret_cast<const float2*>(X + (long long)e3.x * D + lane * 2);
        float2 x4 = *reinterpret_cast<const float2*>(X + (long long)e4.x * D + lane * 2);
        float2 x5 = *reinterpret_cast<const float2*>(X + (long long)e5.x * D + lane * 2);
        float2 x6 = *reinterpret_cast<const float2*>(X + (long long)e6.x * D + lane * 2);
        float2 x7 = *reinterpret_cast<const float2*>(X + (long long)e7.x * D + lane * 2);
        a0 = fmaf(__int_as_float(e0.y), x0.x, a0); a1 = fmaf(__int_as_float(e0.y), x0.y, a1);
        a0 = fmaf(__int_as_float(e1.y), x1.x, a0); a1 = fmaf(__int_as_float(e1.y), x1.y, a1);
        a0 = fmaf(__int_as_float(e2.y), x2.x, a0); a1 = fmaf(__int_as_float(e2.y), x2.y, a1);
        a0 = fmaf(__int_as_float(e3.y), x3.x, a0); a1 = fmaf(__int_as_float(e3.y), x3.y, a1);
        a0 = fmaf(__int_as_float(e4.y), x4.x, a0); a1 = fmaf(__int_as_float(e4.y), x4.y, a1);
        a0 = fmaf(__int_as_float(e5.y), x5.x, a0); a1 = fmaf(__int_as_float(e5.y), x5.y, a1);
        a0 = fmaf(__int_as_float(e6.y), x6.x, a0); a1 = fmaf(__int_as_float(e6.y), x6.y, a1);
        a0 = fmaf(__int_as_float(e7.y), x7.x, a0); a1 = fmaf(__int_as_float(e7.y), x7.y, a1);
    }
    for (; j < deg; j++) {
        int2 ee = __ldg(ep + j);
        float2 x = *reinterpret_cast<const float2*>(X + (long long)ee.x * D + lane * 2);
        float v = __int_as_float(ee.y);
        a0 = fmaf(v, x.x, a0); a1 = fmaf(v, x.y, a1);
    }
    *reinterpret_cast<float2*>(Y + (long long)gw * D + lane * 2) = make_float2(a0, a1);
}

// Warp-per-batch-index ELL gather (rows = bu[i]); skips duplicate batch slots.
__global__ __launch_bounds__(256)
void spmm_batch_kernel(const int* __restrict__ cnt, const int2* __restrict__ ell,
                       const float* __restrict__ X, const int* __restrict__ bu,
                       const int* __restrict__ map, float* __restrict__ Y, int B) {
    int gw   = (blockIdx.x * blockDim.x + threadIdx.x) >> 5;
    int lane = threadIdx.x & 31;
    if (gw >= B) return;
    int r = __ldg(bu + gw);
    if (__ldg(map + r) != gw) return;
    int deg = min(__ldg(cnt + r), DEGCAP);
    const int2* ep = ell + (long long)r * DEGCAP;
    float a0 = 0.f, a1 = 0.f;
    int j = 0;
    for (; j + 4 <= deg; j += 4) {
        int2 e0 = __ldg(ep + j);
        int2 e1 = __ldg(ep + j + 1);
        int2 e2 = __ldg(ep + j + 2);
        int2 e3 = __ldg(ep + j + 3);
        float2 x0 = *reinterpret_cast<const float2*>(X + (long long)e0.x * D + lane * 2);
        float2 x1 = *reinterpret_cast<const float2*>(X + (long long)e1.x * D + lane * 2);
        float2 x2 = *reinterpret_cast<const float2*>(X + (long long)e2.x * D + lane * 2);
        float2 x3 = *reinterpret_cast<const float2*>(X + (long long)e3.x * D + lane * 2);
        a0 = fmaf(__int_as_float(e0.y), x0.x, a0); a1 = fmaf(__int_as_float(e0.y), x0.y, a1);
        a0 = fmaf(__int_as_float(e1.y), x1.x, a0); a1 = fmaf(__int_as_float(e1.y), x1.y, a1);
        a0 = fmaf(__int_as_float(e2.y), x2.x, a0); a1 = fmaf(__int_as_float(e2.y), x2.y, a1);
        a0 = fmaf(__int_as_float(e3.y), x3.x, a0); a1 = fmaf(__int_as_float(e3.y), x3.y, a1);
    }
    for (; j < deg; j++) {
        int2 ee = __ldg(ep + j);
        float2 x = *reinterpret_cast<const float2*>(X + (long long)ee.x * D + lane * 2);
        float v = __int_as_float(ee.y);
        a0 = fmaf(v, x.x, a0); a1 = fmaf(v, x.y, a1);
    }
    *reinterpret_cast<float2*>(Y + (long long)gw * D + lane * 2) = make_float2(a0, a1);
}

// Dense layer: out[r] = relu(concat(A[r], Uin[urow]) @ W + b).
// 64-row tile per block; thread = (rg, cg): 4 rows x 4 cols, 16 accumulators.
__global__ __launch_bounds__(256)
void dense_kernel(const float* __restrict__ A,
                  const float* __restrict__ Uin,
                  const int* __restrict__ bu,
                  const float* __restrict__ W,
                  const float* __restrict__ bvec,
                  float* __restrict__ out,
                  int nrows) {
    extern __shared__ float sm[];
    float* Ws = sm;                 // 8192 floats
    float* bs = sm + 8192;          // 64
    float* xs = sm + 8256;          // 64 * XP

    int tid = threadIdx.x;
    #pragma unroll
    for (int i = 0; i < 8; i++)
        reinterpret_cast<float4*>(Ws)[tid + i * 256] =
            reinterpret_cast<const float4*>(W)[tid + i * 256];
    if (tid < D) bs[tid] = bvec[tid];

    int base = blockIdx.x * 64;
    #pragma unroll
    for (int it = 0; it < 8; it++) {
        int s = it * 256 + tid;
        int r = s >> 5;
        int q = s & 31;
        int row = base + r;
        float4 v = make_float4(0.f, 0.f, 0.f, 0.f);
        if (row < nrows) {
            if (q < 16) {
                v = *reinterpret_cast<const float4*>(A + (long long)row * D + q * 4);
            } else {
                long long ur = bu ? (long long)__ldg(bu + row) : (long long)row;
                v = *reinterpret_cast<const float4*>(Uin + ur * D + (q - 16) * 4);
            }
        }
        *reinterpret_cast<float4*>(&xs[r * XP + q * 4]) = v;
    }
    __syncthreads();

    int cg = tid & 15;
    int rg = tid >> 4;
    const float* xr0 = &xs[(rg * 4 + 0) * XP];
    const float* xr1 = &xs[(rg * 4 + 1) * XP];
    const float* xr2 = &xs[(rg * 4 + 2) * XP];
    const float* xr3 = &xs[(rg * 4 + 3) * XP];

    float4 bv = *reinterpret_cast<const float4*>(&bs[cg * 4]);
    float4 a0 = bv, a1 = bv, a2 = bv, a3 = bv;

    #pragma unroll 4
    for (int k = 0; k < 2 * D; k++) {
        float4 w = *reinterpret_cast<const float4*>(&Ws[k * D + cg * 4]);
        float x0 = xr0[k], x1 = xr1[k], x2 = xr2[k], x3 = xr3[k];
        a0.x = fmaf(x0, w.x, a0.x); a0.y = fmaf(x0, w.y, a0.y);
        a0.z = fmaf(x0, w.z, a0.z); a0.w = fmaf(x0, w.w, a0.w);
        a1.x = fmaf(x1, w.x, a1.x); a1.y = fmaf(x1, w.y, a1.y);
        a1.z = fmaf(x1, w.z, a1.z); a1.w = fmaf(x1, w.w, a1.w);
        a2.x = fmaf(x2, w.x, a2.x); a2.y = fmaf(x2, w.y, a2.y);
        a2.z = fmaf(x2, w.z, a2.z); a2.w = fmaf(x2, w.w, a2.w);
        a3.x = fmaf(x3, w.x, a3.x); a3.y = fmaf(x3, w.y, a3.y);
        a3.z = fmaf(x3, w.z, a3.z); a3.w = fmaf(x3, w.w, a3.w);
    }

    float4 accs[4] = {a0, a1, a2, a3};
    #pragma unroll
    for (int rr = 0; rr < 4; rr++) {
        int row = base + rg * 4 + rr;
        if (row < nrows) {
            float4 a = accs[rr];
            a.x = fmaxf(a.x, 0.f); a.y = fmaxf(a.y, 0.f);
            a.z = fmaxf(a.z, 0.f); a.w = fmaxf(a.w, 0.f);
            *reinterpret_cast<float4*>(out + (long long)row * D + cg * 4) = a;
        }
    }
}

__global__ void gather_kernel(const int* __restrict__ bu,
                              const int* __restrict__ bp,
                              const int* __restrict__ bn,
                              const int* __restrict__ map,
                              const float* __restrict__ gB,
                              const float* __restrict__ rB,
                              const float* __restrict__ V,
                              float* __restrict__ out,
                              int B) {
    int i = blockIdx.x * blockDim.x + threadIdx.x;
    int total = 3 * B * 16;
    if (i >= total) return;
    int sec  = i / (B * 16);
    int rem  = i - sec * (B * 16);
    int r    = rem >> 4;
    int lane = rem & 15;
    float4 res;
    if (sec == 0) {
        long long slot = __ldg(map + __ldg(bu + r));
        float4 a = *reinterpret_cast<const float4*>(gB + slot * D + lane * 4);
        float4 bb = *reinterpret_cast<const float4*>(rB + slot * D + lane * 4);
        res = make_float4(a.x + bb.x, a.y + bb.y, a.z + bb.z, a.w + bb.w);
    } else if (sec == 1) {
        res = *reinterpret_cast<const float4*>(V + (long long)__ldg(bp + r) * D + lane * 4);
    } else {
        res = *reinterpret_cast<const float4*>(V + (long long)__ldg(bn + r) * D + lane * 4);
    }
    reinterpret_cast<float4*>(out)[i] = res;
}

// ---------------------------------------------------------------------------
extern "C" void kernel_launch(void* const* d_in, const int* in_sizes, int n_in,
                              void* d_out, int out_size) {
    const int*   bu    = (const int*)  d_in[0];
    const int*   bp    = (const int*)  d_in[1];
    const int*   bn    = (const int*)  d_in[2];
    const float* U     = (const float*)d_in[3];
    const float* V     = (const float*)d_in[4];
    const float* W0    = (const float*)d_in[5];
    const float* b0    = (const float*)d_in[6];
    const float* W1    = (const float*)d_in[7];
    const float* b1    = (const float*)d_in[8];
    const int*   S_row = (const int*)  d_in[9];
    const int*   S_col = (const int*)  d_in[10];
    const float* S_val = (const float*)d_in[11];
    const int*   R_row = (const int*)  d_in[12];
    const int*   R_col = (const int*)  d_in[13];
    const float* R_val = (const float*)d_in[14];

    int B       = in_sizes[0];
    int n_users = in_sizes[3] / D;
    int s_nnz   = in_sizes[9];
    int r_nnz   = in_sizes[12];

    float *s1, *s2, *aggB, *gB, *rB;
    int *cnt, *map, *rcount;
    unsigned *bitmap;
    int2 *ellS;
    int4 *cedge;
    cudaGetSymbolAddress((void**)&s1,     g_s1);
    cudaGetSymbolAddress((void**)&s2,     g_s2);
    cudaGetSymbolAddress((void**)&aggB,   g_aggB);
    cudaGetSymbolAddress((void**)&gB,     g_gB);
    cudaGetSymbolAddress((void**)&rB,     g_rB);
    cudaGetSymbolAddress((void**)&cnt,    g_cnt);
    cudaGetSymbolAddress((void**)&map,    g_map);
    cudaGetSymbolAddress((void**)&bitmap, g_bitmap);
    cudaGetSymbolAddress((void**)&rcount, g_rcount);
    cudaGetSymbolAddress((void**)&ellS,   g_ellS);
    cudaGetSymbolAddress((void**)&cedge,  g_cedge);

    const int DENSE_SMEM = (8192 + 64 + 64 * XP) * 4;   // 66816 bytes

    // One-time setup (first call is outside graph capture): attribute + stream
    // + events. All-or-nothing: only mark done if every call succeeded, so a
    // transient failure can't leave half-initialized static state behind.
    static bool setup_done = false;
    static cudaStream_t sB = nullptr;
    static cudaEvent_t evInit = nullptr, evMap = nullptr, evR = nullptr;
    if (!setup_done) {
        bool ok = true;
        ok &= (cudaFuncSetAttribute(dense_kernel,
                 cudaFuncAttributeMaxDynamicSharedMemorySize, DENSE_SMEM) == cudaSuccess);
        if (!sB)     ok &= (cudaStreamCreateWithFlags(&sB, cudaStreamNonBlocking) == cudaSuccess);
        if (!evInit) ok &= (cudaEventCreateWithFlags(&evInit, cudaEventDisableTiming) == cudaSuccess);
        if (!evMap)  ok &= (cudaEventCreateWithFlags(&evMap,  cudaEventDisableTiming) == cudaSuccess);
        if (!evR)    ok &= (cudaEventCreateWithFlags(&evR,    cudaEventDisableTiming) == cudaSuccess);
        setup_done = ok;
    }

    int b16 = B * 16;
    int init_n = (n_users > b16) ? n_users : b16;
    int st = (s_nnz + 7) / 8;               // fill: 8 edges/thread
    int rt = (r_nnz + 15) / 16;             // compact: 16 edges/thread
    int wb_full  = (n_users * 32 + 255) / 256;
    int wb_batch = (B * 32 + 255) / 256;

    // --- Stream A: init; fork B ---
    init_kernel<<<(init_n + 255) / 256, 256>>>(cnt, map, bitmap, rB, rcount, n_users, b16);
    cudaEventRecord(evInit, 0);
    cudaStreamWaitEvent(sB, evInit, 0);

    // --- Stream B: lean R chain ---
    map_build_kernel<<<(B + 255) / 256, 256, 0, sB>>>(bu, B, map, bitmap);
    cudaEventRecord(evMap, sB);
    r_compact_kernel<<<(rt + 255) / 256, 256, 0, sB>>>(R_row, R_col, R_val, r_nnz,
                                                       bitmap, map, cedge, rcount);
    r_scatter_kernel<<<2048, 256, 0, sB>>>(cedge, rcount, V, rB);
    cudaEventRecord(evR, sB);

    // --- Stream A: S chain ---
    fill_ell_kernel<<<(st + 255) / 256, 256>>>(S_row, S_col, S_val, s_nnz, cnt, ellS);
    spmm_full_kernel<<<wb_full, 256>>>(cnt, ellS, U, s1, n_users);
    dense_kernel<<<(n_users + 63) / 64, 256, DENSE_SMEM>>>(s1, U, nullptr, W0, b0, s2, n_users);

    cudaStreamWaitEvent(0, evMap, 0);
    spmm_batch_kernel<<<wb_batch, 256>>>(cnt, ellS, s2, bu, map, aggB, B);
    dense_kernel<<<(B + 63) / 64, 256, DENSE_SMEM>>>(aggB, s2, bu, W1, b1, gB, B);

    // --- Join and gather ---
    cudaStreamWaitEvent(0, evR, 0);
    int g_total = 3 * B * 16;
    gather_kernel<<<(g_total + 255) / 256, 256>>>(bu, bp, bn, map, gB, rB, V, (float*)d_out, B);
}